// round 7
// baseline (speedup 1.0000x reference)
#include <cuda_runtime.h>
#include <math.h>
#include <float.h>

// Problem constants
#define NB 8
#define NN 2048
#define NC 128
#define NCH 128     // chunks per batch
#define CSZ 16      // chunk size (NCH*CSZ == NN)
#define NP (NN+1)   // prefix length 2049

// ---------------- scratch (device globals; no allocation) ----------------
__device__ float g_h[NB*NN*NC];        // h = text @ W
__device__ float g_s1[NB*NN];
__device__ float g_s2[NB*NN];
__device__ float g_s2s[NB*NN];         // sorted s2 (ascending, via rank scatter)
__device__ int   g_perm[NB*NN];        // permutation of sort
__device__ float g_wA[NB*NN];          // e^{s2s - m2}
__device__ float g_wB[NB*NN];          // e^{0.2(s2s - m2)}
__device__ float g_m2[NB];
__device__ float g_paf[NB*NP];         // full scalar exclusive prefix of wA; [2048]=total
__device__ float g_pbf[NB*NP];
__device__ float2 g_P[NB*NP*NC];       // packed full vector prefixes (x=A, y=B)
__device__ float2 g_aggr[NB*NCH*NC];   // per-chunk aggregates
__device__ float2 g_incl[NB*NCH*NC];   // per-chunk inclusive prefixes
__device__ int    g_flag[NB*NCH];      // 0=none, 1=aggregate ready, 2=inclusive ready

// ---------------- f32x2 packed-FMA helpers (sm_103a FFMA2) ----------------
__device__ __forceinline__ unsigned long long pack2(float x, float y) {
    unsigned long long r;
    asm("mov.b64 %0, {%1, %2};" : "=l"(r) : "f"(x), "f"(y));
    return r;
}
__device__ __forceinline__ void unpack2(unsigned long long v, float& x, float& y) {
    asm("mov.b64 {%0, %1}, %2;" : "=f"(x), "=f"(y) : "l"(v));
}
__device__ __forceinline__ void ffma2(unsigned long long& d, unsigned long long a, unsigned long long b) {
    asm("fma.rn.f32x2 %0, %1, %2, %0;" : "+l"(d) : "l"(a), "l"(b));
}

// ---------------- Kernel 1: GEMM h = text@W (f32x2), fused s1/s2 ----------------
__global__ void __launch_bounds__(256) gemm_kernel(const float* __restrict__ A,
                                                   const float* __restrict__ W,
                                                   const float* __restrict__ avec)
{
    __shared__ float As[16][64];
    __shared__ float Bs[16][128];
    const int b  = blockIdx.y;
    const int m0 = blockIdx.x * 64;
    const int tid = threadIdx.x;
    const int tx = tid & 31;
    const int ty = tid >> 5;
    const float* Ab = A + (size_t)(b*NN + m0) * NC;

    unsigned long long acc2[4][4];
#pragma unroll
    for (int p = 0; p < 4; p++)
#pragma unroll
        for (int j = 0; j < 4; j++) acc2[p][j] = 0ull;

    const int ar = tid >> 2;
    const int ac = (tid & 3) * 4;

    for (int k0 = 0; k0 < 128; k0 += 16) {
        float4 av = *(const float4*)(Ab + (size_t)ar*NC + k0 + ac);
        As[ac+0][ar] = av.x; As[ac+1][ar] = av.y;
        As[ac+2][ar] = av.z; As[ac+3][ar] = av.w;
#pragma unroll
        for (int it = 0; it < 2; it++) {
            int idx = tid + 256*it;
            int brr = idx >> 5, bcc = (idx & 31) * 4;
            *(float4*)&Bs[brr][bcc] = *(const float4*)(W + (size_t)(k0+brr)*NC + bcc);
        }
        __syncthreads();
#pragma unroll
        for (int kk = 0; kk < 16; kk++) {
            float4 a03 = *(const float4*)&As[kk][ty*8];
            float4 a47 = *(const float4*)&As[kk][ty*8 + 4];
            float4 bv  = *(const float4*)&Bs[kk][tx*4];
            unsigned long long ap[4];
            ap[0] = pack2(a03.x, a03.y); ap[1] = pack2(a03.z, a03.w);
            ap[2] = pack2(a47.x, a47.y); ap[3] = pack2(a47.z, a47.w);
            unsigned long long bd[4];
            bd[0] = pack2(bv.x, bv.x); bd[1] = pack2(bv.y, bv.y);
            bd[2] = pack2(bv.z, bv.z); bd[3] = pack2(bv.w, bv.w);
#pragma unroll
            for (int p = 0; p < 4; p++)
#pragma unroll
                for (int j = 0; j < 4; j++) ffma2(acc2[p][j], ap[p], bd[j]);
        }
        __syncthreads();
    }

    float acc[8][4];
#pragma unroll
    for (int p = 0; p < 4; p++)
#pragma unroll
        for (int j = 0; j < 4; j++) unpack2(acc2[p][j], acc[2*p][j], acc[2*p+1][j]);

    float a1[4], a2[4];
#pragma unroll
    for (int j = 0; j < 4; j++) { a1[j] = avec[tx*4+j]; a2[j] = avec[128 + tx*4+j]; }

#pragma unroll
    for (int i = 0; i < 8; i++) {
        int row = m0 + ty*8 + i;
        float4 v = make_float4(acc[i][0], acc[i][1], acc[i][2], acc[i][3]);
        *(float4*)(g_h + (size_t)(b*NN + row)*NC + tx*4) = v;
        float d1 = acc[i][0]*a1[0] + acc[i][1]*a1[1] + acc[i][2]*a1[2] + acc[i][3]*a1[3];
        float d2 = acc[i][0]*a2[0] + acc[i][1]*a2[1] + acc[i][2]*a2[2] + acc[i][3]*a2[3];
#pragma unroll
        for (int off = 16; off > 0; off >>= 1) {
            d1 += __shfl_down_sync(0xffffffffu, d1, off);
            d2 += __shfl_down_sync(0xffffffffu, d2, off);
        }
        if (tx == 0) { g_s1[b*NN + row] = d1; g_s2[b*NN + row] = d2; }
    }
}

// ---------------- Kernel 2: rank-scatter "sort" (whole-chip parallel, float4 compares) ----------------
__global__ void __launch_bounds__(128) rank_kernel()
{
    __shared__ float keys[NN];
    __shared__ float red[4];
    const int b = blockIdx.y, tid = threadIdx.x;
    const int j = blockIdx.x * 128 + tid;

    for (int i = tid; i < NN; i += 128) keys[i] = g_s2[b*NN + i];
    __syncthreads();

    float mx = -FLT_MAX;
    for (int i = tid; i < NN; i += 128) mx = fmaxf(mx, keys[i]);
#pragma unroll
    for (int off = 16; off > 0; off >>= 1)
        mx = fmaxf(mx, __shfl_xor_sync(0xffffffffu, mx, off));
    if ((tid & 31) == 0) red[tid >> 5] = mx;
    __syncthreads();
    const float m2v = fmaxf(fmaxf(red[0], red[1]), fmaxf(red[2], red[3]));
    if (blockIdx.x == 0 && tid == 0) g_m2[b] = m2v;

    const float k = keys[j];
    const float4* k4 = (const float4*)keys;
    int rank = 0;
#pragma unroll 4
    for (int q = 0; q < NN/4; q++) {
        float4 v = k4[q];
        int jj = q*4;
        rank += (v.x < k) || (v.x == k && jj+0 < j);
        rank += (v.y < k) || (v.y == k && jj+1 < j);
        rank += (v.z < k) || (v.z == k && jj+2 < j);
        rank += (v.w < k) || (v.w == k && jj+3 < j);
    }

    const float s = k - m2v;
    const int o = b*NN + rank;
    g_s2s[o]  = k;
    g_perm[o] = j;
    g_wA[o]   = expf(s);
    g_wB[o]   = expf(0.2f * s);
}

// ---------------- Kernel 3: scalar weight prefixes (per batch) + flag reset ----------------
__global__ void __launch_bounds__(128) spf_kernel()
{
    __shared__ float sa_sh[4], sb_sh[4];
    const int b = blockIdx.x, c = threadIdx.x;
    const int lane = c & 31, w = c >> 5;
    const int base = b*NN + c*CSZ;

    g_flag[b*NCH + c] = 0;   // reset lookback flags for this replay

    float va[CSZ], vb[CSZ];
    float sa = 0.f, sb = 0.f;
#pragma unroll
    for (int r = 0; r < CSZ; r++) {
        va[r] = g_wA[base + r];
        vb[r] = g_wB[base + r];
        sa += va[r]; sb += vb[r];
    }
    float ia = sa, ib = sb;
#pragma unroll
    for (int off = 1; off < 32; off <<= 1) {
        float na = __shfl_up_sync(0xffffffffu, ia, off);
        float nb = __shfl_up_sync(0xffffffffu, ib, off);
        if (lane >= off) { ia += na; ib += nb; }
    }
    if (lane == 31) { sa_sh[w] = ia; sb_sh[w] = ib; }
    __syncthreads();
    float offA = 0.f, offB = 0.f;
#pragma unroll
    for (int ww = 0; ww < 4; ww++) {
        if (ww < w) { offA += sa_sh[ww]; offB += sb_sh[ww]; }
    }
    float ra = offA + ia - sa;
    float rb = offB + ib - sb;
#pragma unroll
    for (int r = 0; r < CSZ; r++) {
        g_paf[b*NP + c*CSZ + r] = ra;
        g_pbf[b*NP + c*CSZ + r] = rb;
        ra += va[r]; rb += vb[r];
    }
    if (c == 127) {
        g_paf[b*NP + NN] = ra;
        g_pbf[b*NP + NN] = rb;
    }
}

// ---------------- Kernel 4: fused chunk + deterministic lookback scan + expand ----------------
// grid (NCH, NB) x 128 threads. excl(c) = incl(c-8) + agg(c-7..c-1), fixed pattern
// -> bitwise deterministic regardless of timing. All 1024 blocks co-resident.
#define LBSTRIDE 8
__global__ void __launch_bounds__(128) fused_kernel()
{
    __shared__ float wa[CSZ], wb[CSZ];
    __shared__ int js[CSZ];
    const int b = blockIdx.y, c = blockIdx.x, f = threadIdx.x;
    const int base = b*NN + c*CSZ;
    if (f < CSZ) {
        wa[f] = g_wA[base + f];
        wb[f] = g_wB[base + f];
        js[f] = g_perm[base + f];
    }
    __syncthreads();

    // own aggregate; keep h rows in registers for the expand pass
    float hv[CSZ];
#pragma unroll
    for (int r = 0; r < CSZ; r++) hv[r] = g_h[(size_t)(b*NN + js[r])*NC + f];
    float aA = 0.f, aB = 0.f;
#pragma unroll
    for (int r = 0; r < CSZ; r++) { aA = fmaf(wa[r], hv[r], aA); aB = fmaf(wb[r], hv[r], aB); }

    const size_t vidx = (size_t)(b*NCH + c)*NC + f;
    g_aggr[vidx] = make_float2(aA, aB);
    __threadfence();
    __syncthreads();
    volatile int* vflag = g_flag;
    if (f == 0) vflag[b*NCH + c] = 1;

    // deterministic lookback for exclusive base
    float eA = 0.f, eB = 0.f;
    if (c > 0) {
        const int start = (c >= LBSTRIDE) ? (c - LBSTRIDE) : 0;
        if (f == 0) {
            if (c >= LBSTRIDE) while (vflag[b*NCH + start] < 2) { }
            for (int p = (c >= LBSTRIDE) ? (start + 1) : 0; p < c; p++)
                while (vflag[b*NCH + p] < 1) { }
        }
        __syncthreads();
        __threadfence();
        if (c >= LBSTRIDE) {
            float2 v = __ldcg(&g_incl[(size_t)(b*NCH + start)*NC + f]);
            eA = v.x; eB = v.y;
        }
        for (int p = (c >= LBSTRIDE) ? (c - LBSTRIDE + 1) : 0; p < c; p++) {
            float2 v = __ldcg(&g_aggr[(size_t)(b*NCH + p)*NC + f]);
            eA += v.x; eB += v.y;
        }
    }

    // publish inclusive
    g_incl[vidx] = make_float2(eA + aA, eB + aB);
    __threadfence();
    __syncthreads();
    if (f == 0) vflag[b*NCH + c] = 2;

    // expand full vector prefixes from registers
    float runA = eA, runB = eB;
    size_t p = (size_t)(b*NP + c*CSZ)*NC + f;
#pragma unroll
    for (int r = 0; r < CSZ; r++) {
        g_P[p] = make_float2(runA, runB);
        runA = fmaf(wa[r], hv[r], runA);
        runB = fmaf(wb[r], hv[r], runB);
        p += NC;
    }
    if (c == NCH-1) g_P[p] = make_float2(runA, runB);  // index NN: grand totals
}

// ---------------- Kernel 5: per-query output ----------------
__global__ void __launch_bounds__(128) query_kernel(float* __restrict__ out)
{
    __shared__ float s2sh[NN];
    __shared__ int   ks[16];
    __shared__ float s1s[16];
    const int b = blockIdx.y, f = threadIdx.x;
    const int qbase = blockIdx.x * 16;
    for (int i = f; i < NN; i += 128) s2sh[i] = g_s2s[b*NN + i];
    __syncthreads();

    if (f < 16) {
        const int i = qbase + f;
        const float s1v = g_s1[b*NN + i];
        s1s[f] = s1v;
        const float t = -s1v;
        int k = 0;
#pragma unroll
        for (int st = 2048; st > 0; st >>= 1) {
            int nk = k + st;
            if (nk <= NN && s2sh[nk-1] <= t) k = nk;
        }
        ks[f] = k;
    }
    __syncthreads();

    const float m2v = g_m2[b];
    const float taf = g_P[(size_t)(b*NP + NN)*NC + f].x;
    const float tas = g_paf[b*NP + NN];

#pragma unroll 4
    for (int qi = 0; qi < 16; qi++) {
        const int i = qbase + qi;
        const int k = ks[qi];
        const float s1v = s1s[qi];
        const float2 Pk = g_P[(size_t)(b*NP + k)*NC + f];
        const float sap = g_paf[b*NP + k];
        const float sbp = g_pbf[b*NP + k];
        const float SA = taf - Pk.x, SB = Pk.y;
        const float sa = tas - sap, sb = sbp;
        const float u = s1v + m2v;
        float hp;
        if (u > 0.f) {
            float inv = expf(-0.8f * u);
            hp = (SA + inv*SB) / (sa + inv*sb);
        } else {
            float fc = expf(0.8f * u);
            hp = (fc*SA + SB) / (fc*sa + sb);
        }
        const float hvi = g_h[(size_t)(b*NN + i)*NC + f];
        const float x = hp + 0.2f * hvi;
        out[(size_t)(b*NN + i)*NC + f] = (x > 0.f) ? x : expm1f(x);
    }
}

// ---------------- launch ----------------
extern "C" void kernel_launch(void* const* d_in, const int* in_sizes, int n_in,
                              void* d_out, int out_size)
{
    int iText = 0, iW = 2, iA = 3;
    for (int i = 0; i < n_in; i++) {
        if (in_sizes[i] == NB*NN*NC) iText = i;
        else if (in_sizes[i] == NC*NC) iW = i;
        else if (in_sizes[i] == 2*NC) iA = i;
    }
    const float* text = (const float*)d_in[iText];
    const float* W    = (const float*)d_in[iW];
    const float* avec = (const float*)d_in[iA];
    float* out = (float*)d_out;

    gemm_kernel<<<dim3(NN/64, NB), 256>>>(text, W, avec);
    rank_kernel<<<dim3(16, NB), 128>>>();
    spf_kernel<<<NB, 128>>>();
    fused_kernel<<<dim3(NCH, NB), 128>>>();
    query_kernel<<<dim3(NN/16, NB), 128>>>(out);
}

// round 8
// speedup vs baseline: 1.6258x; 1.6258x over previous
#include <cuda_runtime.h>
#include <math.h>
#include <float.h>

// Problem constants
#define NB 8
#define NN 2048
#define NC 128
#define NCH 128     // chunks per batch
#define CSZ 16      // chunk size (NCH*CSZ == NN)
#define NP (NN+1)   // prefix length 2049

// ---------------- scratch (device globals; no allocation) ----------------
__device__ float g_h[NB*NN*NC];        // h = text @ W
__device__ float g_s1[NB*NN];
__device__ float g_s2[NB*NN];
__device__ float g_s2s[NB*NN];         // sorted s2 (ascending, via rank scatter)
__device__ int   g_perm[NB*NN];        // permutation of sort
__device__ float g_wA[NB*NN];          // e^{s2s - m2}
__device__ float g_wB[NB*NN];          // e^{0.2(s2s - m2)}
__device__ float g_m2[NB];
__device__ float2 g_ch[NB*(NCH+1)*NC]; // chunk sums -> exclusive prefixes; [NCH]=total
__device__ float g_paf[NB*NP];         // full scalar exclusive prefix of wA; [2048]=total
__device__ float g_pbf[NB*NP];
__device__ float2 g_P[NB*NP*NC];       // packed full vector prefixes (x=A, y=B)
__device__ int   g_cnt_rank[NB];       // arrival counters (reset by gemm)
__device__ int   g_cnt_chunk[NB];

// ---------------- f32x2 packed-FMA helpers (sm_103a FFMA2) ----------------
__device__ __forceinline__ unsigned long long pack2(float x, float y) {
    unsigned long long r;
    asm("mov.b64 %0, {%1, %2};" : "=l"(r) : "f"(x), "f"(y));
    return r;
}
__device__ __forceinline__ void unpack2(unsigned long long v, float& x, float& y) {
    asm("mov.b64 {%0, %1}, %2;" : "=f"(x), "=f"(y) : "l"(v));
}
__device__ __forceinline__ void ffma2(unsigned long long& d, unsigned long long a, unsigned long long b) {
    asm("fma.rn.f32x2 %0, %1, %2, %0;" : "+l"(d) : "l"(a), "l"(b));
}

// ---------------- Kernel 1: GEMM h = text@W (f32x2), fused s1/s2 ----------------
__global__ void __launch_bounds__(256) gemm_kernel(const float* __restrict__ A,
                                                   const float* __restrict__ W,
                                                   const float* __restrict__ avec)
{
    // reset arrival counters for this replay (visible to later kernels at kernel end)
    if (blockIdx.x == 0 && blockIdx.y == 0 && threadIdx.x < NB) {
        g_cnt_rank[threadIdx.x] = 0;
        g_cnt_chunk[threadIdx.x] = 0;
    }

    __shared__ float As[16][64];
    __shared__ float Bs[16][128];
    const int b  = blockIdx.y;
    const int m0 = blockIdx.x * 64;
    const int tid = threadIdx.x;
    const int tx = tid & 31;
    const int ty = tid >> 5;
    const float* Ab = A + (size_t)(b*NN + m0) * NC;

    unsigned long long acc2[4][4];
#pragma unroll
    for (int p = 0; p < 4; p++)
#pragma unroll
        for (int j = 0; j < 4; j++) acc2[p][j] = 0ull;

    const int ar = tid >> 2;
    const int ac = (tid & 3) * 4;

    for (int k0 = 0; k0 < 128; k0 += 16) {
        float4 av = *(const float4*)(Ab + (size_t)ar*NC + k0 + ac);
        As[ac+0][ar] = av.x; As[ac+1][ar] = av.y;
        As[ac+2][ar] = av.z; As[ac+3][ar] = av.w;
#pragma unroll
        for (int it = 0; it < 2; it++) {
            int idx = tid + 256*it;
            int brr = idx >> 5, bcc = (idx & 31) * 4;
            *(float4*)&Bs[brr][bcc] = *(const float4*)(W + (size_t)(k0+brr)*NC + bcc);
        }
        __syncthreads();
#pragma unroll
        for (int kk = 0; kk < 16; kk++) {
            float4 a03 = *(const float4*)&As[kk][ty*8];
            float4 a47 = *(const float4*)&As[kk][ty*8 + 4];
            float4 bv  = *(const float4*)&Bs[kk][tx*4];
            unsigned long long ap[4];
            ap[0] = pack2(a03.x, a03.y); ap[1] = pack2(a03.z, a03.w);
            ap[2] = pack2(a47.x, a47.y); ap[3] = pack2(a47.z, a47.w);
            unsigned long long bd[4];
            bd[0] = pack2(bv.x, bv.x); bd[1] = pack2(bv.y, bv.y);
            bd[2] = pack2(bv.z, bv.z); bd[3] = pack2(bv.w, bv.w);
#pragma unroll
            for (int p = 0; p < 4; p++)
#pragma unroll
                for (int j = 0; j < 4; j++) ffma2(acc2[p][j], ap[p], bd[j]);
        }
        __syncthreads();
    }

    float acc[8][4];
#pragma unroll
    for (int p = 0; p < 4; p++)
#pragma unroll
        for (int j = 0; j < 4; j++) unpack2(acc2[p][j], acc[2*p][j], acc[2*p+1][j]);

    float a1[4], a2[4];
#pragma unroll
    for (int j = 0; j < 4; j++) { a1[j] = avec[tx*4+j]; a2[j] = avec[128 + tx*4+j]; }

#pragma unroll
    for (int i = 0; i < 8; i++) {
        int row = m0 + ty*8 + i;
        float4 v = make_float4(acc[i][0], acc[i][1], acc[i][2], acc[i][3]);
        *(float4*)(g_h + (size_t)(b*NN + row)*NC + tx*4) = v;
        float d1 = acc[i][0]*a1[0] + acc[i][1]*a1[1] + acc[i][2]*a1[2] + acc[i][3]*a1[3];
        float d2 = acc[i][0]*a2[0] + acc[i][1]*a2[1] + acc[i][2]*a2[2] + acc[i][3]*a2[3];
#pragma unroll
        for (int off = 16; off > 0; off >>= 1) {
            d1 += __shfl_down_sync(0xffffffffu, d1, off);
            d2 += __shfl_down_sync(0xffffffffu, d2, off);
        }
        if (tx == 0) { g_s1[b*NN + row] = d1; g_s2[b*NN + row] = d2; }
    }
}

// ---------------- Kernel 2: rank-scatter "sort" + last-block scalar prefixes ----------------
__global__ void __launch_bounds__(128) rank_kernel()
{
    __shared__ float keys[NN];
    __shared__ float red[4];
    __shared__ int slast;
    const int b = blockIdx.y, tid = threadIdx.x;
    const int j = blockIdx.x * 128 + tid;

    for (int i = tid; i < NN; i += 128) keys[i] = g_s2[b*NN + i];
    __syncthreads();

    float mx = -FLT_MAX;
    for (int i = tid; i < NN; i += 128) mx = fmaxf(mx, keys[i]);
#pragma unroll
    for (int off = 16; off > 0; off >>= 1)
        mx = fmaxf(mx, __shfl_xor_sync(0xffffffffu, mx, off));
    if ((tid & 31) == 0) red[tid >> 5] = mx;
    __syncthreads();
    const float m2v = fmaxf(fmaxf(red[0], red[1]), fmaxf(red[2], red[3]));
    if (blockIdx.x == 0 && tid == 0) g_m2[b] = m2v;

    const float k = keys[j];
    const float4* k4 = (const float4*)keys;
    int rank = 0;
#pragma unroll 4
    for (int q = 0; q < NN/4; q++) {
        float4 v = k4[q];
        int jj = q*4;
        rank += (v.x < k) || (v.x == k && jj+0 < j);
        rank += (v.y < k) || (v.y == k && jj+1 < j);
        rank += (v.z < k) || (v.z == k && jj+2 < j);
        rank += (v.w < k) || (v.w == k && jj+3 < j);
    }

    const float s = k - m2v;
    const int o = b*NN + rank;
    const float wa0 = expf(s), wb0 = expf(0.2f * s);
    g_s2s[o]  = k;
    g_perm[o] = j;
    g_wA[o]   = wa0;
    g_wB[o]   = wb0;

    // ---- last block of this batch computes scalar weight prefixes ----
    __threadfence();
    __syncthreads();
    if (tid == 0) slast = (atomicAdd(&g_cnt_rank[b], 1) == 15);
    __syncthreads();
    if (!slast) return;
    __threadfence();

    {
        __shared__ float sa_sh[4], sb_sh[4];
        const int c = tid;                 // chunk id 0..127
        const int lane = c & 31, w = c >> 5;
        const int base = b*NN + c*CSZ;

        float va[CSZ], vb[CSZ];
        float sa = 0.f, sb = 0.f;
#pragma unroll
        for (int r = 0; r < CSZ; r++) {
            va[r] = __ldcg(&g_wA[base + r]);
            vb[r] = __ldcg(&g_wB[base + r]);
            sa += va[r]; sb += vb[r];
        }
        float ia = sa, ib = sb;
#pragma unroll
        for (int off = 1; off < 32; off <<= 1) {
            float na = __shfl_up_sync(0xffffffffu, ia, off);
            float nb = __shfl_up_sync(0xffffffffu, ib, off);
            if (lane >= off) { ia += na; ib += nb; }
        }
        if (lane == 31) { sa_sh[w] = ia; sb_sh[w] = ib; }
        __syncthreads();
        float offA = 0.f, offB = 0.f;
#pragma unroll
        for (int ww = 0; ww < 4; ww++)
            if (ww < w) { offA += sa_sh[ww]; offB += sb_sh[ww]; }
        float ra = offA + ia - sa;
        float rb = offB + ib - sb;
#pragma unroll
        for (int r = 0; r < CSZ; r++) {
            g_paf[b*NP + c*CSZ + r] = ra;
            g_pbf[b*NP + c*CSZ + r] = rb;
            ra += va[r]; rb += vb[r];
        }
        if (c == 127) {
            g_paf[b*NP + NN] = ra;
            g_pbf[b*NP + NN] = rb;
        }
    }
}

// ---------------- Kernel 3: vector chunk sums + last-block exclusive scan ----------------
__global__ void __launch_bounds__(128) chunk_kernel()
{
    __shared__ int   js[CSZ];
    __shared__ float swa[CSZ], swb[CSZ];
    __shared__ int slast;
    const int b = blockIdx.y, c = blockIdx.x, f = threadIdx.x;
    const int base = b*NN + c*CSZ;
    if (f < CSZ) {
        js[f]  = g_perm[base + f];
        swa[f] = g_wA[base + f];
        swb[f] = g_wB[base + f];
    }
    __syncthreads();
    float aA = 0.f, aB = 0.f;
#pragma unroll
    for (int r = 0; r < CSZ; r++) {
        float hv = g_h[(size_t)(b*NN + js[r])*NC + f];
        aA = fmaf(swa[r], hv, aA);
        aB = fmaf(swb[r], hv, aB);
    }
    g_ch[(size_t)(b*(NCH+1)+c)*NC + f] = make_float2(aA, aB);

    // ---- last block of this batch converts aggregates -> exclusive prefixes ----
    __threadfence();
    __syncthreads();
    if (f == 0) slast = (atomicAdd(&g_cnt_chunk[b], 1) == NCH-1);
    __syncthreads();
    if (!slast) return;
    __threadfence();

    {
        const size_t sbase = (size_t)(b*(NCH+1))*NC + f;   // thread f owns feature f
        float rA = 0.f, rB = 0.f;
        for (int c0 = 0; c0 < NCH; c0 += 16) {
            float2 v[16];
#pragma unroll
            for (int u = 0; u < 16; u++) v[u] = __ldcg(&g_ch[sbase + (size_t)(c0+u)*NC]);
#pragma unroll
            for (int u = 0; u < 16; u++) {
                float2 cur = v[u];
                g_ch[sbase + (size_t)(c0+u)*NC] = make_float2(rA, rB);
                rA += cur.x; rB += cur.y;
            }
        }
        g_ch[sbase + (size_t)NCH*NC] = make_float2(rA, rB);  // totals
    }
}

// ---------------- Kernel 4: expand full vector prefixes ----------------
__global__ void __launch_bounds__(128) expand_kernel()
{
    __shared__ float wa[CSZ], wb[CSZ];
    __shared__ int js[CSZ];
    const int b = blockIdx.y, c = blockIdx.x, f = threadIdx.x;
    const int base = b*NN + c*CSZ;
    if (f < CSZ) {
        wa[f] = g_wA[base + f];
        wb[f] = g_wB[base + f];
        js[f] = g_perm[base + f];
    }
    __syncthreads();

    float2 run = g_ch[(size_t)(b*(NCH+1)+c)*NC + f];
    float runA = run.x, runB = run.y;

    size_t p = (size_t)(b*NP + c*CSZ)*NC + f;
#pragma unroll
    for (int r = 0; r < CSZ; r++) {
        g_P[p] = make_float2(runA, runB);
        float hv = g_h[(size_t)(b*NN + js[r])*NC + f];
        runA = fmaf(wa[r], hv, runA);
        runB = fmaf(wb[r], hv, runB);
        p += NC;
    }
    if (c == NCH-1) g_P[p] = make_float2(runA, runB);  // index NN: grand totals
}

// ---------------- Kernel 5: per-query output ----------------
__global__ void __launch_bounds__(128) query_kernel(float* __restrict__ out)
{
    __shared__ float s2sh[NN];
    __shared__ int   ks[16];
    __shared__ float s1s[16];
    const int b = blockIdx.y, f = threadIdx.x;
    const int qbase = blockIdx.x * 16;
    for (int i = f; i < NN; i += 128) s2sh[i] = g_s2s[b*NN + i];
    __syncthreads();

    if (f < 16) {
        const int i = qbase + f;
        const float s1v = g_s1[b*NN + i];
        s1s[f] = s1v;
        const float t = -s1v;
        int k = 0;
#pragma unroll
        for (int st = 2048; st > 0; st >>= 1) {
            int nk = k + st;
            if (nk <= NN && s2sh[nk-1] <= t) k = nk;
        }
        ks[f] = k;
    }
    __syncthreads();

    const float m2v = g_m2[b];
    const float taf = g_P[(size_t)(b*NP + NN)*NC + f].x;
    const float tas = g_paf[b*NP + NN];

#pragma unroll 4
    for (int qi = 0; qi < 16; qi++) {
        const int i = qbase + qi;
        const int k = ks[qi];
        const float s1v = s1s[qi];
        const float2 Pk = g_P[(size_t)(b*NP + k)*NC + f];
        const float sap = g_paf[b*NP + k];
        const float sbp = g_pbf[b*NP + k];
        const float SA = taf - Pk.x, SB = Pk.y;
        const float sa = tas - sap, sb = sbp;
        const float u = s1v + m2v;
        float hp;
        if (u > 0.f) {
            float inv = expf(-0.8f * u);
            hp = (SA + inv*SB) / (sa + inv*sb);
        } else {
            float fc = expf(0.8f * u);
            hp = (fc*SA + SB) / (fc*sa + sb);
        }
        const float hvi = g_h[(size_t)(b*NN + i)*NC + f];
        const float x = hp + 0.2f * hvi;
        out[(size_t)(b*NN + i)*NC + f] = (x > 0.f) ? x : expm1f(x);
    }
}

// ---------------- launch ----------------
extern "C" void kernel_launch(void* const* d_in, const int* in_sizes, int n_in,
                              void* d_out, int out_size)
{
    int iText = 0, iW = 2, iA = 3;
    for (int i = 0; i < n_in; i++) {
        if (in_sizes[i] == NB*NN*NC) iText = i;
        else if (in_sizes[i] == NC*NC) iW = i;
        else if (in_sizes[i] == 2*NC) iA = i;
    }
    const float* text = (const float*)d_in[iText];
    const float* W    = (const float*)d_in[iW];
    const float* avec = (const float*)d_in[iA];
    float* out = (float*)d_out;

    gemm_kernel<<<dim3(NN/64, NB), 256>>>(text, W, avec);
    rank_kernel<<<dim3(16, NB), 128>>>();
    chunk_kernel<<<dim3(NCH, NB), 128>>>();
    expand_kernel<<<dim3(NCH, NB), 128>>>();
    query_kernel<<<dim3(NN/16, NB), 128>>>(out);
}

// round 9
// speedup vs baseline: 1.8295x; 1.1253x over previous
#include <cuda_runtime.h>
#include <math.h>
#include <float.h>

// Problem constants
#define NB 8
#define NN 2048
#define NC 128
#define NCH 128     // chunks per batch
#define CSZ 16      // chunk size (NCH*CSZ == NN)
#define NP (NN+1)   // prefix length 2049

// ---------------- scratch (device globals; no allocation) ----------------
__device__ float g_h[NB*NN*NC];        // h = text @ W
__device__ float g_s1[NB*NN];
__device__ float g_s2[NB*NN];
__device__ float g_s2s[NB*NN];         // sorted s2 (ascending, via rank scatter)
__device__ int   g_perm[NB*NN];        // permutation of sort
__device__ float g_wA[NB*NN];          // e^{s2s - m2}
__device__ float g_wB[NB*NN];          // e^{0.2(s2s - m2)}
__device__ float g_m2[NB];
__device__ float2 g_ch[NB*(NCH+1)*NC]; // chunk sums -> exclusive prefixes; [NCH]=total
__device__ float g_paf[NB*NP];         // full scalar exclusive prefix of wA; [2048]=total
__device__ float g_pbf[NB*NP];
__device__ float2 g_P[NB*NP*NC];       // packed full vector prefixes (x=A, y=B)

// ---------------- f32x2 packed-FMA helpers (sm_103a FFMA2) ----------------
__device__ __forceinline__ unsigned long long pack2(float x, float y) {
    unsigned long long r;
    asm("mov.b64 %0, {%1, %2};" : "=l"(r) : "f"(x), "f"(y));
    return r;
}
__device__ __forceinline__ void unpack2(unsigned long long v, float& x, float& y) {
    asm("mov.b64 {%0, %1}, %2;" : "=f"(x), "=f"(y) : "l"(v));
}
__device__ __forceinline__ void ffma2(unsigned long long& d, unsigned long long a, unsigned long long b) {
    asm("fma.rn.f32x2 %0, %1, %2, %0;" : "+l"(d) : "l"(a), "l"(b));
}

// ---------------- Kernel 1: GEMM h = text@W (f32x2), fused s1/s2 ----------------
__global__ void __launch_bounds__(256) gemm_kernel(const float* __restrict__ A,
                                                   const float* __restrict__ W,
                                                   const float* __restrict__ avec)
{
    __shared__ float As[16][64];
    __shared__ float Bs[16][128];
    const int b  = blockIdx.y;
    const int m0 = blockIdx.x * 64;
    const int tid = threadIdx.x;
    const int tx = tid & 31;
    const int ty = tid >> 5;
    const float* Ab = A + (size_t)(b*NN + m0) * NC;

    unsigned long long acc2[4][4];
#pragma unroll
    for (int p = 0; p < 4; p++)
#pragma unroll
        for (int j = 0; j < 4; j++) acc2[p][j] = 0ull;

    const int ar = tid >> 2;
    const int ac = (tid & 3) * 4;

    for (int k0 = 0; k0 < 128; k0 += 16) {
        float4 av = *(const float4*)(Ab + (size_t)ar*NC + k0 + ac);
        As[ac+0][ar] = av.x; As[ac+1][ar] = av.y;
        As[ac+2][ar] = av.z; As[ac+3][ar] = av.w;
#pragma unroll
        for (int it = 0; it < 2; it++) {
            int idx = tid + 256*it;
            int brr = idx >> 5, bcc = (idx & 31) * 4;
            *(float4*)&Bs[brr][bcc] = *(const float4*)(W + (size_t)(k0+brr)*NC + bcc);
        }
        __syncthreads();
#pragma unroll
        for (int kk = 0; kk < 16; kk++) {
            float4 a03 = *(const float4*)&As[kk][ty*8];
            float4 a47 = *(const float4*)&As[kk][ty*8 + 4];
            float4 bv  = *(const float4*)&Bs[kk][tx*4];
            unsigned long long ap[4];
            ap[0] = pack2(a03.x, a03.y); ap[1] = pack2(a03.z, a03.w);
            ap[2] = pack2(a47.x, a47.y); ap[3] = pack2(a47.z, a47.w);
            unsigned long long bd[4];
            bd[0] = pack2(bv.x, bv.x); bd[1] = pack2(bv.y, bv.y);
            bd[2] = pack2(bv.z, bv.z); bd[3] = pack2(bv.w, bv.w);
#pragma unroll
            for (int p = 0; p < 4; p++)
#pragma unroll
                for (int j = 0; j < 4; j++) ffma2(acc2[p][j], ap[p], bd[j]);
        }
        __syncthreads();
    }

    float acc[8][4];
#pragma unroll
    for (int p = 0; p < 4; p++)
#pragma unroll
        for (int j = 0; j < 4; j++) unpack2(acc2[p][j], acc[2*p][j], acc[2*p+1][j]);

    float a1[4], a2[4];
#pragma unroll
    for (int j = 0; j < 4; j++) { a1[j] = avec[tx*4+j]; a2[j] = avec[128 + tx*4+j]; }

#pragma unroll
    for (int i = 0; i < 8; i++) {
        int row = m0 + ty*8 + i;
        float4 v = make_float4(acc[i][0], acc[i][1], acc[i][2], acc[i][3]);
        *(float4*)(g_h + (size_t)(b*NN + row)*NC + tx*4) = v;
        float d1 = acc[i][0]*a1[0] + acc[i][1]*a1[1] + acc[i][2]*a1[2] + acc[i][3]*a1[3];
        float d2 = acc[i][0]*a2[0] + acc[i][1]*a2[1] + acc[i][2]*a2[2] + acc[i][3]*a2[3];
#pragma unroll
        for (int off = 16; off > 0; off >>= 1) {
            d1 += __shfl_down_sync(0xffffffffu, d1, off);
            d2 += __shfl_down_sync(0xffffffffu, d2, off);
        }
        if (tx == 0) { g_s1[b*NN + row] = d1; g_s2[b*NN + row] = d2; }
    }
}

// ---------------- Kernel 2: rank-scatter "sort" (whole-chip parallel, float4 compares) ----------------
__global__ void __launch_bounds__(128) rank_kernel()
{
    __shared__ float keys[NN];
    __shared__ float red[4];
    const int b = blockIdx.y, tid = threadIdx.x;
    const int j = blockIdx.x * 128 + tid;

    for (int i = tid; i < NN; i += 128) keys[i] = g_s2[b*NN + i];
    __syncthreads();

    float mx = -FLT_MAX;
    for (int i = tid; i < NN; i += 128) mx = fmaxf(mx, keys[i]);
#pragma unroll
    for (int off = 16; off > 0; off >>= 1)
        mx = fmaxf(mx, __shfl_xor_sync(0xffffffffu, mx, off));
    if ((tid & 31) == 0) red[tid >> 5] = mx;
    __syncthreads();
    const float m2v = fmaxf(fmaxf(red[0], red[1]), fmaxf(red[2], red[3]));
    if (blockIdx.x == 0 && tid == 0) g_m2[b] = m2v;

    const float k = keys[j];
    const float4* k4 = (const float4*)keys;
    int rank = 0;
#pragma unroll 4
    for (int q = 0; q < NN/4; q++) {
        float4 v = k4[q];
        int jj = q*4;
        rank += (v.x < k) || (v.x == k && jj+0 < j);
        rank += (v.y < k) || (v.y == k && jj+1 < j);
        rank += (v.z < k) || (v.z == k && jj+2 < j);
        rank += (v.w < k) || (v.w == k && jj+3 < j);
    }

    const float s = k - m2v;
    const int o = b*NN + rank;
    g_s2s[o]  = k;
    g_perm[o] = j;
    g_wA[o]   = expf(s);
    g_wB[o]   = expf(0.2f * s);
}

// ---------------- Kernel 3: scalar weight prefixes (per batch) ----------------
__global__ void __launch_bounds__(128) spf_kernel()
{
    __shared__ float sa_sh[4], sb_sh[4];
    const int b = blockIdx.x, c = threadIdx.x;
    const int lane = c & 31, w = c >> 5;
    const int base = b*NN + c*CSZ;

    float va[CSZ], vb[CSZ];
    float sa = 0.f, sb = 0.f;
#pragma unroll
    for (int r = 0; r < CSZ; r++) {
        va[r] = g_wA[base + r];
        vb[r] = g_wB[base + r];
        sa += va[r]; sb += vb[r];
    }
    float ia = sa, ib = sb;
#pragma unroll
    for (int off = 1; off < 32; off <<= 1) {
        float na = __shfl_up_sync(0xffffffffu, ia, off);
        float nb = __shfl_up_sync(0xffffffffu, ib, off);
        if (lane >= off) { ia += na; ib += nb; }
    }
    if (lane == 31) { sa_sh[w] = ia; sb_sh[w] = ib; }
    __syncthreads();
    float offA = 0.f, offB = 0.f;
#pragma unroll
    for (int ww = 0; ww < 4; ww++)
        if (ww < w) { offA += sa_sh[ww]; offB += sb_sh[ww]; }
    float ra = offA + ia - sa;
    float rb = offB + ib - sb;
#pragma unroll
    for (int r = 0; r < CSZ; r++) {
        g_paf[b*NP + c*CSZ + r] = ra;
        g_pbf[b*NP + c*CSZ + r] = rb;
        ra += va[r]; rb += vb[r];
    }
    if (c == 127) {
        g_paf[b*NP + NN] = ra;
        g_pbf[b*NP + NN] = rb;
    }
}

// ---------------- Kernel 4: vector chunk sums (prefetched h rows) ----------------
__global__ void __launch_bounds__(128) chunk_kernel()
{
    __shared__ int   js[CSZ];
    __shared__ float swa[CSZ], swb[CSZ];
    const int b = blockIdx.y, c = blockIdx.x, f = threadIdx.x;
    const int base = b*NN + c*CSZ;
    if (f < CSZ) {
        js[f]  = g_perm[base + f];
        swa[f] = g_wA[base + f];
        swb[f] = g_wB[base + f];
    }
    __syncthreads();
    float hv[CSZ];
#pragma unroll
    for (int r = 0; r < CSZ; r++) hv[r] = g_h[(size_t)(b*NN + js[r])*NC + f];
    float aA = 0.f, aB = 0.f;
#pragma unroll
    for (int r = 0; r < CSZ; r++) {
        aA = fmaf(swa[r], hv[r], aA);
        aB = fmaf(swb[r], hv[r], aB);
    }
    g_ch[(size_t)(b*(NCH+1)+c)*NC + f] = make_float2(aA, aB);
}

// ---------------- Kernel 5: coalesced serial scan over chunks ----------------
// grid NB x 128 threads; thread f owns feature f; for each chunk index the
// 128 threads hit 128 consecutive float2 (1KB burst). 16-deep load batching.
__global__ void __launch_bounds__(128) scan_kernel()
{
    const int b = blockIdx.x, f = threadIdx.x;
    const size_t sbase = (size_t)(b*(NCH+1))*NC + f;
    float rA = 0.f, rB = 0.f;
    for (int c0 = 0; c0 < NCH; c0 += 16) {
        float2 v[16];
#pragma unroll
        for (int u = 0; u < 16; u++) v[u] = g_ch[sbase + (size_t)(c0+u)*NC];
#pragma unroll
        for (int u = 0; u < 16; u++) {
            float2 cur = v[u];
            g_ch[sbase + (size_t)(c0+u)*NC] = make_float2(rA, rB);
            rA += cur.x; rB += cur.y;
        }
    }
    g_ch[sbase + (size_t)NCH*NC] = make_float2(rA, rB);  // totals
}

// ---------------- Kernel 6: expand full vector prefixes (prefetched h rows) ----------------
__global__ void __launch_bounds__(128) expand_kernel()
{
    __shared__ float wa[CSZ], wb[CSZ];
    __shared__ int js[CSZ];
    const int b = blockIdx.y, c = blockIdx.x, f = threadIdx.x;
    const int base = b*NN + c*CSZ;
    if (f < CSZ) {
        wa[f] = g_wA[base + f];
        wb[f] = g_wB[base + f];
        js[f] = g_perm[base + f];
    }
    __syncthreads();

    float hv[CSZ];
#pragma unroll
    for (int r = 0; r < CSZ; r++) hv[r] = g_h[(size_t)(b*NN + js[r])*NC + f];

    float2 run = g_ch[(size_t)(b*(NCH+1)+c)*NC + f];
    float runA = run.x, runB = run.y;

    size_t p = (size_t)(b*NP + c*CSZ)*NC + f;
#pragma unroll
    for (int r = 0; r < CSZ; r++) {
        g_P[p] = make_float2(runA, runB);
        runA = fmaf(wa[r], hv[r], runA);
        runB = fmaf(wb[r], hv[r], runB);
        p += NC;
    }
    if (c == NCH-1) g_P[p] = make_float2(runA, runB);  // index NN: grand totals
}

// ---------------- Kernel 7: per-query output ----------------
__global__ void __launch_bounds__(128) query_kernel(float* __restrict__ out)
{
    __shared__ float s2sh[NN];
    __shared__ int   ks[16];
    __shared__ float s1s[16];
    const int b = blockIdx.y, f = threadIdx.x;
    const int qbase = blockIdx.x * 16;
    for (int i = f; i < NN; i += 128) s2sh[i] = g_s2s[b*NN + i];
    __syncthreads();

    if (f < 16) {
        const int i = qbase + f;
        const float s1v = g_s1[b*NN + i];
        s1s[f] = s1v;
        const float t = -s1v;
        int k = 0;
#pragma unroll
        for (int st = 2048; st > 0; st >>= 1) {
            int nk = k + st;
            if (nk <= NN && s2sh[nk-1] <= t) k = nk;
        }
        ks[f] = k;
    }
    __syncthreads();

    const float m2v = g_m2[b];
    const float taf = g_P[(size_t)(b*NP + NN)*NC + f].x;
    const float tas = g_paf[b*NP + NN];

#pragma unroll 4
    for (int qi = 0; qi < 16; qi++) {
        const int i = qbase + qi;
        const int k = ks[qi];
        const float s1v = s1s[qi];
        const float2 Pk = g_P[(size_t)(b*NP + k)*NC + f];
        const float sap = g_paf[b*NP + k];
        const float sbp = g_pbf[b*NP + k];
        const float SA = taf - Pk.x, SB = Pk.y;
        const float sa = tas - sap, sb = sbp;
        const float u = s1v + m2v;
        float hp;
        if (u > 0.f) {
            float inv = expf(-0.8f * u);
            hp = (SA + inv*SB) / (sa + inv*sb);
        } else {
            float fc = expf(0.8f * u);
            hp = (fc*SA + SB) / (fc*sa + sb);
        }
        const float hvi = g_h[(size_t)(b*NN + i)*NC + f];
        const float x = hp + 0.2f * hvi;
        out[(size_t)(b*NN + i)*NC + f] = (x > 0.f) ? x : expm1f(x);
    }
}

// ---------------- launch ----------------
extern "C" void kernel_launch(void* const* d_in, const int* in_sizes, int n_in,
                              void* d_out, int out_size)
{
    int iText = 0, iW = 2, iA = 3;
    for (int i = 0; i < n_in; i++) {
        if (in_sizes[i] == NB*NN*NC) iText = i;
        else if (in_sizes[i] == NC*NC) iW = i;
        else if (in_sizes[i] == 2*NC) iA = i;
    }
    const float* text = (const float*)d_in[iText];
    const float* W    = (const float*)d_in[iW];
    const float* avec = (const float*)d_in[iA];
    float* out = (float*)d_out;

    gemm_kernel<<<dim3(NN/64, NB), 256>>>(text, W, avec);
    rank_kernel<<<dim3(16, NB), 128>>>();
    spf_kernel<<<NB, 128>>>();
    chunk_kernel<<<dim3(NCH, NB), 128>>>();
    scan_kernel<<<NB, 128>>>();
    expand_kernel<<<dim3(NCH, NB), 128>>>();
    query_kernel<<<dim3(NN/16, NB), 128>>>(out);
}

// round 10
// speedup vs baseline: 2.0175x; 1.1028x over previous
#include <cuda_runtime.h>
#include <math.h>
#include <float.h>

// Problem constants
#define NB 8
#define NN 2048
#define NC 128
#define NCH 128     // chunks per batch
#define CSZ 16      // chunk size (NCH*CSZ == NN)
#define NP (NN+1)   // prefix length 2049

// ---------------- scratch (device globals; no allocation) ----------------
__device__ float g_h[NB*NN*NC];        // h = text @ W
__device__ float g_s1[NB*NN];
__device__ float g_s2[NB*NN];
__device__ float g_s2s[NB*NN];         // sorted s2 (ascending, via rank scatter)
__device__ int   g_perm[NB*NN];        // permutation of sort
__device__ float g_wA[NB*NN];          // e^{s2s - m2}
__device__ float g_wB[NB*NN];          // e^{0.2(s2s - m2)}
__device__ float g_m2[NB];
__device__ float2 g_ch[NB*(NCH+1)*NC]; // chunk aggregates -> exclusive bases; [NCH]=totals
__device__ float g_paf[NB*NP];         // full scalar exclusive prefix of wA; [2048]=total
__device__ float g_pbf[NB*NP];
__device__ float2 g_P[NB*NP*NC];       // intra-chunk RELATIVE vector prefixes (x=A, y=B)

// ---------------- f32x2 packed-FMA helpers (sm_103a FFMA2) ----------------
__device__ __forceinline__ unsigned long long pack2(float x, float y) {
    unsigned long long r;
    asm("mov.b64 %0, {%1, %2};" : "=l"(r) : "f"(x), "f"(y));
    return r;
}
__device__ __forceinline__ void unpack2(unsigned long long v, float& x, float& y) {
    asm("mov.b64 {%0, %1}, %2;" : "=f"(x), "=f"(y) : "l"(v));
}
__device__ __forceinline__ void ffma2(unsigned long long& d, unsigned long long a, unsigned long long b) {
    asm("fma.rn.f32x2 %0, %1, %2, %0;" : "+l"(d) : "l"(a), "l"(b));
}

// ---------------- Kernel 1: GEMM h = text@W (f32x2), fused s1/s2 ----------------
__global__ void __launch_bounds__(256) gemm_kernel(const float* __restrict__ A,
                                                   const float* __restrict__ W,
                                                   const float* __restrict__ avec)
{
    __shared__ float As[16][64];
    __shared__ float Bs[16][128];
    const int b  = blockIdx.y;
    const int m0 = blockIdx.x * 64;
    const int tid = threadIdx.x;
    const int tx = tid & 31;
    const int ty = tid >> 5;
    const float* Ab = A + (size_t)(b*NN + m0) * NC;

    unsigned long long acc2[4][4];
#pragma unroll
    for (int p = 0; p < 4; p++)
#pragma unroll
        for (int j = 0; j < 4; j++) acc2[p][j] = 0ull;

    const int ar = tid >> 2;
    const int ac = (tid & 3) * 4;

    for (int k0 = 0; k0 < 128; k0 += 16) {
        float4 av = *(const float4*)(Ab + (size_t)ar*NC + k0 + ac);
        As[ac+0][ar] = av.x; As[ac+1][ar] = av.y;
        As[ac+2][ar] = av.z; As[ac+3][ar] = av.w;
#pragma unroll
        for (int it = 0; it < 2; it++) {
            int idx = tid + 256*it;
            int brr = idx >> 5, bcc = (idx & 31) * 4;
            *(float4*)&Bs[brr][bcc] = *(const float4*)(W + (size_t)(k0+brr)*NC + bcc);
        }
        __syncthreads();
#pragma unroll
        for (int kk = 0; kk < 16; kk++) {
            float4 a03 = *(const float4*)&As[kk][ty*8];
            float4 a47 = *(const float4*)&As[kk][ty*8 + 4];
            float4 bv  = *(const float4*)&Bs[kk][tx*4];
            unsigned long long ap[4];
            ap[0] = pack2(a03.x, a03.y); ap[1] = pack2(a03.z, a03.w);
            ap[2] = pack2(a47.x, a47.y); ap[3] = pack2(a47.z, a47.w);
            unsigned long long bd[4];
            bd[0] = pack2(bv.x, bv.x); bd[1] = pack2(bv.y, bv.y);
            bd[2] = pack2(bv.z, bv.z); bd[3] = pack2(bv.w, bv.w);
#pragma unroll
            for (int p = 0; p < 4; p++)
#pragma unroll
                for (int j = 0; j < 4; j++) ffma2(acc2[p][j], ap[p], bd[j]);
        }
        __syncthreads();
    }

    float acc[8][4];
#pragma unroll
    for (int p = 0; p < 4; p++)
#pragma unroll
        for (int j = 0; j < 4; j++) unpack2(acc2[p][j], acc[2*p][j], acc[2*p+1][j]);

    float a1[4], a2[4];
#pragma unroll
    for (int j = 0; j < 4; j++) { a1[j] = avec[tx*4+j]; a2[j] = avec[128 + tx*4+j]; }

#pragma unroll
    for (int i = 0; i < 8; i++) {
        int row = m0 + ty*8 + i;
        float4 v = make_float4(acc[i][0], acc[i][1], acc[i][2], acc[i][3]);
        *(float4*)(g_h + (size_t)(b*NN + row)*NC + tx*4) = v;
        float d1 = acc[i][0]*a1[0] + acc[i][1]*a1[1] + acc[i][2]*a1[2] + acc[i][3]*a1[3];
        float d2 = acc[i][0]*a2[0] + acc[i][1]*a2[1] + acc[i][2]*a2[2] + acc[i][3]*a2[3];
#pragma unroll
        for (int off = 16; off > 0; off >>= 1) {
            d1 += __shfl_down_sync(0xffffffffu, d1, off);
            d2 += __shfl_down_sync(0xffffffffu, d2, off);
        }
        if (tx == 0) { g_s1[b*NN + row] = d1; g_s2[b*NN + row] = d2; }
    }
}

// ---------------- Kernel 2: rank-scatter "sort" (whole-chip parallel) ----------------
__global__ void __launch_bounds__(128) rank_kernel()
{
    __shared__ float keys[NN];
    __shared__ float red[4];
    const int b = blockIdx.y, tid = threadIdx.x;
    const int j = blockIdx.x * 128 + tid;

    for (int i = tid; i < NN; i += 128) keys[i] = g_s2[b*NN + i];
    __syncthreads();

    float mx = -FLT_MAX;
    for (int i = tid; i < NN; i += 128) mx = fmaxf(mx, keys[i]);
#pragma unroll
    for (int off = 16; off > 0; off >>= 1)
        mx = fmaxf(mx, __shfl_xor_sync(0xffffffffu, mx, off));
    if ((tid & 31) == 0) red[tid >> 5] = mx;
    __syncthreads();
    const float m2v = fmaxf(fmaxf(red[0], red[1]), fmaxf(red[2], red[3]));
    if (blockIdx.x == 0 && tid == 0) g_m2[b] = m2v;

    const float k = keys[j];
    const float4* k4 = (const float4*)keys;
    int rank = 0;
#pragma unroll 4
    for (int q = 0; q < NN/4; q++) {
        float4 v = k4[q];
        int jj = q*4;
        rank += (v.x < k) || (v.x == k && jj+0 < j);
        rank += (v.y < k) || (v.y == k && jj+1 < j);
        rank += (v.z < k) || (v.z == k && jj+2 < j);
        rank += (v.w < k) || (v.w == k && jj+3 < j);
    }

    const float s = k - m2v;
    const int o = b*NN + rank;
    g_s2s[o]  = k;
    g_perm[o] = j;
    g_wA[o]   = expf(s);
    g_wB[o]   = expf(0.2f * s);
}

// ---------------- Kernel 3: relative expand (single pass over h) ----------------
// grid (NCH, NB) x 128. Writes intra-chunk RELATIVE prefixes to g_P and the
// chunk aggregate to g_ch. No cross-chunk dependency -> fully parallel.
__global__ void __launch_bounds__(128) relexpand_kernel()
{
    __shared__ float wa[CSZ], wb[CSZ];
    __shared__ int js[CSZ];
    const int b = blockIdx.y, c = blockIdx.x, f = threadIdx.x;
    const int base = b*NN + c*CSZ;
    if (f < CSZ) {
        wa[f] = g_wA[base + f];
        wb[f] = g_wB[base + f];
        js[f] = g_perm[base + f];
    }
    __syncthreads();

    float hv[CSZ];
#pragma unroll
    for (int r = 0; r < CSZ; r++) hv[r] = g_h[(size_t)(b*NN + js[r])*NC + f];

    float runA = 0.f, runB = 0.f;
    size_t p = (size_t)(b*NP + c*CSZ)*NC + f;
#pragma unroll
    for (int r = 0; r < CSZ; r++) {
        g_P[p] = make_float2(runA, runB);
        runA = fmaf(wa[r], hv[r], runA);
        runB = fmaf(wb[r], hv[r], runB);
        p += NC;
    }
    // chunk aggregate
    g_ch[(size_t)(b*(NCH+1)+c)*NC + f] = make_float2(runA, runB);
    // k == NN maps to chunk NCH (totals base) with zero relative part
    if (c == NCH-1) g_P[p] = make_float2(0.f, 0.f);
}

// ---------------- Kernel 4: fused chunk-scan + scalar weight prefixes ----------------
// grid NB x 128 threads. Part A: thread f scans feature f over 128 chunk
// aggregates (coalesced 1KB bursts, 16-deep batches). Part B: thread c
// builds scalar weight prefixes for chunk c. Independent parts.
__global__ void __launch_bounds__(128) scanspf_kernel()
{
    const int b = blockIdx.x, t = threadIdx.x;

    // --- Part A: vector chunk scan (thread t = feature) ---
    {
        const size_t sbase = (size_t)(b*(NCH+1))*NC + t;
        float rA = 0.f, rB = 0.f;
        for (int c0 = 0; c0 < NCH; c0 += 16) {
            float2 v[16];
#pragma unroll
            for (int u = 0; u < 16; u++) v[u] = g_ch[sbase + (size_t)(c0+u)*NC];
#pragma unroll
            for (int u = 0; u < 16; u++) {
                float2 cur = v[u];
                g_ch[sbase + (size_t)(c0+u)*NC] = make_float2(rA, rB);
                rA += cur.x; rB += cur.y;
            }
        }
        g_ch[sbase + (size_t)NCH*NC] = make_float2(rA, rB);  // totals
    }

    // --- Part B: scalar weight prefixes (thread t = chunk) ---
    {
        __shared__ float sa_sh[4], sb_sh[4];
        const int c = t;
        const int lane = c & 31, w = c >> 5;
        const int wbase = b*NN + c*CSZ;

        float va[CSZ], vb[CSZ];
        float sa = 0.f, sb = 0.f;
#pragma unroll
        for (int r = 0; r < CSZ; r++) {
            va[r] = g_wA[wbase + r];
            vb[r] = g_wB[wbase + r];
            sa += va[r]; sb += vb[r];
        }
        float ia = sa, ib = sb;
#pragma unroll
        for (int off = 1; off < 32; off <<= 1) {
            float na = __shfl_up_sync(0xffffffffu, ia, off);
            float nb = __shfl_up_sync(0xffffffffu, ib, off);
            if (lane >= off) { ia += na; ib += nb; }
        }
        if (lane == 31) { sa_sh[w] = ia; sb_sh[w] = ib; }
        __syncthreads();
        float offA = 0.f, offB = 0.f;
#pragma unroll
        for (int ww = 0; ww < 4; ww++)
            if (ww < w) { offA += sa_sh[ww]; offB += sb_sh[ww]; }
        float ra = offA + ia - sa;
        float rb = offB + ib - sb;
#pragma unroll
        for (int r = 0; r < CSZ; r++) {
            g_paf[b*NP + c*CSZ + r] = ra;
            g_pbf[b*NP + c*CSZ + r] = rb;
            ra += va[r]; rb += vb[r];
        }
        if (c == 127) {
            g_paf[b*NP + NN] = ra;
            g_pbf[b*NP + NN] = rb;
        }
    }
}

// ---------------- Kernel 5: per-query output (base + relative prefix) ----------------
__global__ void __launch_bounds__(128) query_kernel(float* __restrict__ out)
{
    __shared__ float s2sh[NN];
    __shared__ int   ks[16];
    __shared__ float s1s[16];
    const int b = blockIdx.y, f = threadIdx.x;
    const int qbase = blockIdx.x * 16;
    for (int i = f; i < NN; i += 128) s2sh[i] = g_s2s[b*NN + i];
    __syncthreads();

    if (f < 16) {
        const int i = qbase + f;
        const float s1v = g_s1[b*NN + i];
        s1s[f] = s1v;
        const float t = -s1v;
        int k = 0;
#pragma unroll
        for (int st = 2048; st > 0; st >>= 1) {
            int nk = k + st;
            if (nk <= NN && s2sh[nk-1] <= t) k = nk;
        }
        ks[f] = k;
    }
    __syncthreads();

    const float m2v = g_m2[b];
    const float taf = g_ch[(size_t)(b*(NCH+1)+NCH)*NC + f].x;
    const float tas = g_paf[b*NP + NN];

#pragma unroll 4
    for (int qi = 0; qi < 16; qi++) {
        const int i = qbase + qi;
        const int k = ks[qi];
        const float s1v = s1s[qi];
        const int c = k >> 4;                    // k==NN -> c==NCH (totals base)
        const float2 bse = g_ch[(size_t)(b*(NCH+1)+c)*NC + f];
        const float2 rel = g_P[(size_t)(b*NP + k)*NC + f];
        const float PAk = bse.x + rel.x;
        const float PBk = bse.y + rel.y;
        const float sap = g_paf[b*NP + k];
        const float sbp = g_pbf[b*NP + k];
        const float SA = taf - PAk, SB = PBk;
        const float sa = tas - sap, sb = sbp;
        const float u = s1v + m2v;
        float hp;
        if (u > 0.f) {
            float inv = expf(-0.8f * u);
            hp = (SA + inv*SB) / (sa + inv*sb);
        } else {
            float fc = expf(0.8f * u);
            hp = (fc*SA + SB) / (fc*sa + sb);
        }
        const float hvi = g_h[(size_t)(b*NN + i)*NC + f];
        const float x = hp + 0.2f * hvi;
        out[(size_t)(b*NN + i)*NC + f] = (x > 0.f) ? x : expm1f(x);
    }
}

// ---------------- launch ----------------
extern "C" void kernel_launch(void* const* d_in, const int* in_sizes, int n_in,
                              void* d_out, int out_size)
{
    int iText = 0, iW = 2, iA = 3;
    for (int i = 0; i < n_in; i++) {
        if (in_sizes[i] == NB*NN*NC) iText = i;
        else if (in_sizes[i] == NC*NC) iW = i;
        else if (in_sizes[i] == 2*NC) iA = i;
    }
    const float* text = (const float*)d_in[iText];
    const float* W    = (const float*)d_in[iW];
    const float* avec = (const float*)d_in[iA];
    float* out = (float*)d_out;

    gemm_kernel<<<dim3(NN/64, NB), 256>>>(text, W, avec);
    rank_kernel<<<dim3(16, NB), 128>>>();
    relexpand_kernel<<<dim3(NCH, NB), 128>>>();
    scanspf_kernel<<<NB, 128>>>();
    query_kernel<<<dim3(NN/16, NB), 128>>>(out);
}